// round 10
// baseline (speedup 1.0000x reference)
#include <cuda_runtime.h>
#include <cstdint>

// Fixed problem shape
#define NB 2048
#define ND 16384
#define NF4 (ND / 4)              // 4096 float4 per row
#define NBLK 128                  // persistent blocks, 1/SM, all co-resident
#define TPB 256
#define ROWS_B (NB / NBLK)        // 16 rows per block
#define CPT (NF4 / TPB)           // 16 column chunks of 256 float4
#define REG_ROWS 2                // rows 0..1 cached in registers
#define SMEM_H_ROW 2              // row 2 cached in shared

// Scratch (__device__ globals; zero-init, no allocation in kernel_launch)
__device__ float g_psum[NBLK * ND];   // 8MB per-block column partials
__device__ float g_psq [NBLK * ND];   // 8MB
__device__ float g_nmean[ND];
__device__ float g_nvar [ND];
__device__ float g_varpart[NBLK];
__device__ int   g_bar1, g_bar2, g_done;   // self-resetting

__device__ __forceinline__ float score_of(float hv, float m, float iv) {
    float d = __fadd_rn(hv, -m);
    return __fmul_rn(__fmul_rn(d, d), iv);
}

__global__ void __launch_bounds__(TPB, 1)
k_fused(const float* __restrict__ h, const float* __restrict__ hmean,
        const float* __restrict__ hvar, float* __restrict__ out) {
    // dynamic smem: [0,4096) h row 2 | [4096,8192) mean | [8192,12288) inv
    extern __shared__ float4 dyn[];
    float4* sm_h    = dyn;
    float4* sm_mean = dyn + NF4;
    float4* sm_inv  = dyn + 2 * NF4;
    __shared__ float4 sps[TPB], spq[TPB];           // phase-2 scratch (8KB)
    __shared__ float  sred[TPB];
    __shared__ unsigned long long wkey[TPB / 32];

    const int b = blockIdx.x;
    const int t = threadIdx.x;
    const float4* hp  = reinterpret_cast<const float4*>(h)   + (size_t)b * ROWS_B * NF4;
    float4*       op  = reinterpret_cast<float4*>      (out) + (size_t)b * ROWS_B * NF4;
    float4*       ps4 = reinterpret_cast<float4*>(g_psum) + (size_t)b * NF4;
    float4*       pq4 = reinterpret_cast<float4*>(g_psq)  + (size_t)b * NF4;

    float4 a[REG_ROWS * CPT];   // 32 float4 = 128 regs: rows 0..1

    // ------------- Phase 1: read slab once; partial column stats -------------
#pragma unroll
    for (int c = 0; c < CPT; ++c) {
        float4 s = make_float4(0.f, 0.f, 0.f, 0.f);
        float4 q = make_float4(0.f, 0.f, 0.f, 0.f);
#pragma unroll
        for (int r = 0; r < ROWS_B; ++r) {
            const float4* p = &hp[(size_t)r * NF4 + c * TPB + t];
            // on-chip-cached rows: evict-first; L2-cached rows: default (keep)
            float4 v = (r <= SMEM_H_ROW) ? __ldcs(p) : *p;
            s.x += v.x;       s.y += v.y;       s.z += v.z;       s.w += v.w;
            q.x += v.x * v.x; q.y += v.y * v.y; q.z += v.z * v.z; q.w += v.w * v.w;
            if (r < REG_ROWS)          a[c * REG_ROWS + r] = v;
            else if (r == SMEM_H_ROW)  sm_h[c * TPB + t]   = v;
        }
        __stcs(&ps4[c * TPB + t], s);
        __stcs(&pq4[c * TPB + t], q);
    }

    // ------------- Grid barrier 1 (128 blocks, 1/SM, co-resident) ------------
    __syncthreads();
    if (t == 0) {
        __threadfence();
        atomicAdd(&g_bar1, 1);
        while (atomicAdd(&g_bar1, 0) < NBLK) {}
        __threadfence();
    }
    __syncthreads();

    // ------------- Phase 2: finish stats (all 128 blocks, 32 cols each) ------
    {
        const int lane = t & 31;
        const int g    = t >> 5;                    // 8 groups of 32 threads
        const int col4 = b * 32 + lane;             // this block's f4 columns
        float4 ss = make_float4(0.f, 0.f, 0.f, 0.f);
        float4 qq = make_float4(0.f, 0.f, 0.f, 0.f);
        const float4* P = reinterpret_cast<const float4*>(g_psum);
        const float4* Q = reinterpret_cast<const float4*>(g_psq);
#pragma unroll 4
        for (int i = g * 16; i < g * 16 + 16; ++i) {
            float4 aa = __ldcs(&P[(size_t)i * NF4 + col4]);
            float4 bb = __ldcs(&Q[(size_t)i * NF4 + col4]);
            ss.x += aa.x; ss.y += aa.y; ss.z += aa.z; ss.w += aa.w;
            qq.x += bb.x; qq.y += bb.y; qq.z += bb.z; qq.w += bb.w;
        }
        sps[t] = ss;
        spq[t] = qq;
    }
    __syncthreads();
    if (t < 32) {
        float4 ss = sps[t], qq = spq[t];
#pragma unroll
        for (int g = 1; g < 8; ++g) {               // fixed order: deterministic
            float4 aa = sps[g * 32 + t], bb = spq[g * 32 + t];
            ss.x += aa.x; ss.y += aa.y; ss.z += aa.z; ss.w += aa.w;
            qq.x += bb.x; qq.y += bb.y; qq.z += bb.z; qq.w += bb.w;
        }
        const float invB    = 1.0f / (float)NB;
        const float U       = 10.0f;
        const float inv11   = 1.0f / 11.0f;
        const float inv1p1  = 1.0f / 1.1f;
        const float invDen  = 1.0f / (U + 1.0f - invB);
        const float coefOld = U - invB;
        const int col4 = b * 32 + t;

        float4 hm = *(reinterpret_cast<const float4*>(hmean) + col4);
        float4 hv = *(reinterpret_cast<const float4*>(hvar)  + col4);
        float4 nm, nv;
        {
            float mu, var, d;
            mu = ss.x * invB; var = qq.x * invB - mu * mu; d = mu - hm.x;
            nv.x = (hv.x * coefOld + var + d * d * inv1p1) * invDen;
            nm.x = (hm.x * U + mu) * inv11;
            mu = ss.y * invB; var = qq.y * invB - mu * mu; d = mu - hm.y;
            nv.y = (hv.y * coefOld + var + d * d * inv1p1) * invDen;
            nm.y = (hm.y * U + mu) * inv11;
            mu = ss.z * invB; var = qq.z * invB - mu * mu; d = mu - hm.z;
            nv.z = (hv.z * coefOld + var + d * d * inv1p1) * invDen;
            nm.z = (hm.z * U + mu) * inv11;
            mu = ss.w * invB; var = qq.w * invB - mu * mu; d = mu - hm.w;
            nv.w = (hv.w * coefOld + var + d * d * inv1p1) * invDen;
            nm.w = (hm.w * U + mu) * inv11;
        }
        reinterpret_cast<float4*>(g_nmean)[col4] = nm;
        reinterpret_cast<float4*>(g_nvar )[col4] = nv;

        float vs = nv.x + nv.y + nv.z + nv.w;
#pragma unroll
        for (int off = 16; off > 0; off >>= 1)
            vs += __shfl_down_sync(0xFFFFFFFFu, vs, off);
        if (t == 0) g_varpart[b] = vs;
    }

    // ------------- Grid barrier 2 --------------------------------------------
    __syncthreads();
    if (t == 0) {
        __threadfence();
        atomicAdd(&g_bar2, 1);
        while (atomicAdd(&g_bar2, 0) < NBLK) {}
        __threadfence();
    }
    __syncthreads();

    // addend = mean(new_var)/100 (deterministic fixed tree, same in all blocks)
    if (t < NBLK) sred[t] = g_varpart[t];
    __syncthreads();
#pragma unroll
    for (int off = 64; off > 0; off >>= 1) {
        if (t < off) sred[t] += sred[t + off];
        __syncthreads();
    }
    const float addend = sred[0] / (float)ND * 0.01f;

    // fill smem mean/inv (16MB L2 traffic chip-wide)
#pragma unroll
    for (int j = t; j < NF4; j += TPB) {
        float4 m  = __ldg(&reinterpret_cast<const float4*>(g_nmean)[j]);
        float4 nv = __ldg(&reinterpret_cast<const float4*>(g_nvar )[j]);
        float4 iv;
        iv.x = 1.0f / (nv.x + addend);
        iv.y = 1.0f / (nv.y + addend);
        iv.z = 1.0f / (nv.z + addend);
        iv.w = 1.0f / (nv.w + addend);
        sm_mean[j] = m;
        sm_inv[j]  = iv;
    }
    __syncthreads();

    // ------------- Phase 3: score + write + per-row argmax fixup -------------
    const int lane = t & 31;
    const int warp = t >> 5;

#pragma unroll
    for (int r = 0; r < ROWS_B; ++r) {
        float best = -1.0f;                 // scores >= 0
        int   bidx = 0;
#pragma unroll
        for (int c = 0; c < CPT; ++c) {
            const int j = c * TPB + t;      // f4 column index, ascending in c
            float4 v;
            if (r < REG_ROWS)           v = a[c * REG_ROWS + r];
            else if (r == SMEM_H_ROW)   v = sm_h[j];
            else                        v = hp[(size_t)r * NF4 + j];  // L2 hit
            __stcs(&op[(size_t)r * NF4 + j], v);
            float4 m  = sm_mean[j];
            float4 iv = sm_inv[j];
            float s0 = score_of(v.x, m.x, iv.x);
            float s1 = score_of(v.y, m.y, iv.y);
            float s2 = score_of(v.z, m.z, iv.z);
            float s3 = score_of(v.w, m.w, iv.w);
            float mx = fmaxf(fmaxf(s0, s1), fmaxf(s2, s3));
            if (mx > best) {                // strict >, c ascending: first wins
                best = mx;
                bidx = (j << 2) +
                       ((s0 == best) ? 0 : (s1 == best) ? 1 : (s2 == best) ? 2 : 3);
            }
        }
        // key = score_bits<<32 | ~col : max => max score, tie => lowest col
        unsigned long long key =
            ((unsigned long long)__float_as_uint(best) << 32) |
            (unsigned long long)(0xFFFFFFFFu - (unsigned)bidx);
#pragma unroll
        for (int off = 16; off > 0; off >>= 1) {
            unsigned long long o = __shfl_xor_sync(0xFFFFFFFFu, key, off);
            if (o > key) key = o;
        }
        if (lane == 0) wkey[warp] = key;
        __syncthreads();                    // orders this row's __stcs too
        if (t < 32) {
            unsigned long long k2 = (t < TPB / 32) ? wkey[t] : 0ULL;
#pragma unroll
            for (int off = 16; off > 0; off >>= 1) {
                unsigned long long o = __shfl_xor_sync(0xFFFFFFFFu, k2, off);
                if (o > k2) k2 = o;
            }
            if (t == 0) {
                const int w = (int)(0xFFFFFFFFu - (unsigned)(k2 & 0xFFFFFFFFull));
                out[(size_t)(b * ROWS_B + r) * ND + w] = g_nmean[w];
            }
        }
        __syncthreads();                    // wkey reuse next row
    }

    // ------------- self-reset for graph replay -------------------------------
    if (t == 0) {
        __threadfence();
        int old = atomicAdd(&g_done, 1);
        if (old == NBLK - 1) {              // all blocks past both barriers
            g_bar1 = 0;
            g_bar2 = 0;
            g_done = 0;
        }
    }
}

// ---------------------------------------------------------------------------
extern "C" void kernel_launch(void* const* d_in, const int* in_sizes, int n_in,
                              void* d_out, int out_size) {
    const float* h     = (const float*)d_in[0];
    const float* hmean = (const float*)d_in[1];
    const float* hvar  = (const float*)d_in[2];
    float* out = (float*)d_out;
    (void)in_sizes; (void)n_in; (void)out_size;

    const int smem_bytes = 3 * NF4 * 16;    // 192KB: h row2 + mean + inv
    cudaFuncSetAttribute(k_fused, cudaFuncAttributeMaxDynamicSharedMemorySize,
                         smem_bytes);
    k_fused<<<NBLK, TPB, smem_bytes>>>(h, hmean, hvar, out);
}

// round 11
// speedup vs baseline: 2.3387x; 2.3387x over previous
#include <cuda_runtime.h>

// Fixed problem shape
#define NB 2048
#define ND 16384
#define RSPLIT 64
#define ROWS_PER (NB / RSPLIT)            // 32 rows per partial block
#define FIN_BLOCKS (ND / (256 * 2))       // 32 blocks, 2 cols/thread
#define SI_BLOCKS 64                      // fused scalar+inv: 64 * 256 = 16384

// Scratch (__device__ globals; no allocation allowed)
__device__ float g_psum[RSPLIT * ND];
__device__ float g_psq [RSPLIT * ND];
__device__ float g_nmean[ND];
__device__ float g_nvar [ND];
__device__ float g_inv  [ND];             // 1 / (new_var + addend)
__device__ float g_varpart[FIN_BLOCKS];

// ---------------------------------------------------------------------------
// Pass 1: per-(rowchunk, column) partial sum / sumsq.
// grid = (ND/1024, RSPLIT), block = 256, 4 cols/thread, 32 rows/block.
// (R2-measured configuration.)
// ---------------------------------------------------------------------------
__global__ void __launch_bounds__(256) k_colstats_partial(const float* __restrict__ h) {
    const int c  = (blockIdx.x * 256 + threadIdx.x) * 4;
    const int r0 = blockIdx.y * ROWS_PER;
    float4 s = make_float4(0.f, 0.f, 0.f, 0.f);
    float4 q = make_float4(0.f, 0.f, 0.f, 0.f);
    const float4* hp = reinterpret_cast<const float4*>(h + (size_t)r0 * ND + c);
    const size_t stride4 = ND / 4;
#pragma unroll 8
    for (int r = 0; r < ROWS_PER; ++r) {
        float4 v = __ldcs(&hp[(size_t)r * stride4]);
        s.x += v.x;       s.y += v.y;       s.z += v.z;       s.w += v.w;
        q.x += v.x * v.x; q.y += v.y * v.y; q.z += v.z * v.z; q.w += v.w * v.w;
    }
    *reinterpret_cast<float4*>(g_psum + (size_t)blockIdx.y * ND + c) = s;
    *reinterpret_cast<float4*>(g_psq  + (size_t)blockIdx.y * ND + c) = q;
}

// ---------------------------------------------------------------------------
// Pass 2: finish stats -> new_mean, new_var; partial sum(new_var).
// grid = FIN_BLOCKS (32), block = 256, 2 cols/thread. (R2-measured.)
// ---------------------------------------------------------------------------
__global__ void __launch_bounds__(256) k_colstats_finish(const float* __restrict__ hmean,
                                                         const float* __restrict__ hvar) {
    const int c = (blockIdx.x * 256 + threadIdx.x) * 2;
    float2 s = make_float2(0.f, 0.f);
    float2 q = make_float2(0.f, 0.f);
#pragma unroll 8
    for (int i = 0; i < RSPLIT; ++i) {
        float2 a = *reinterpret_cast<const float2*>(g_psum + (size_t)i * ND + c);
        float2 b = *reinterpret_cast<const float2*>(g_psq  + (size_t)i * ND + c);
        s.x += a.x; s.y += a.y;
        q.x += b.x; q.y += b.y;
    }
    const float invB    = 1.0f / (float)NB;
    const float U       = 10.0f;
    const float inv11   = 1.0f / 11.0f;
    const float inv1p1  = 1.0f / 1.1f;
    const float invDen  = 1.0f / (U + 1.0f - invB);
    const float coefOld = U - invB;

    float2 hm = *reinterpret_cast<const float2*>(hmean + c);
    float2 hv = *reinterpret_cast<const float2*>(hvar  + c);

    float2 nm, nv;
    {
        float mu, var, d;
        mu = s.x * invB; var = q.x * invB - mu * mu; d = mu - hm.x;
        nv.x = (hv.x * coefOld + var + d * d * inv1p1) * invDen;
        nm.x = (hm.x * U + mu) * inv11;
        mu = s.y * invB; var = q.y * invB - mu * mu; d = mu - hm.y;
        nv.y = (hv.y * coefOld + var + d * d * inv1p1) * invDen;
        nm.y = (hm.y * U + mu) * inv11;
    }
    *reinterpret_cast<float2*>(g_nmean + c) = nm;
    *reinterpret_cast<float2*>(g_nvar  + c) = nv;

    __shared__ float sred[256];
    sred[threadIdx.x] = nv.x + nv.y;
    __syncthreads();
    for (int off = 128; off > 0; off >>= 1) {
        if (threadIdx.x < off) sred[threadIdx.x] += sred[threadIdx.x + off];
        __syncthreads();
    }
    if (threadIdx.x == 0) g_varpart[blockIdx.x] = sred[0];
}

// ---------------------------------------------------------------------------
// Pass 3 (fused scalar + inv): every block redundantly reduces the 32 L2-hot
// varpart values to addend, then writes its slice of inv = 1/(nvar+a).
// grid = SI_BLOCKS (64), block = 256, 1 col/thread. (Ran inside R4.)
// ---------------------------------------------------------------------------
__global__ void __launch_bounds__(256) k_scalar_inv() {
    __shared__ float s_add;
    if (threadIdx.x < 32) {
        float v = g_varpart[threadIdx.x];   // FIN_BLOCKS == 32
#pragma unroll
        for (int off = 16; off > 0; off >>= 1)
            v += __shfl_down_sync(0xFFFFFFFFu, v, off);
        if (threadIdx.x == 0) s_add = (v / (float)ND) * 0.01f;
    }
    __syncthreads();
    const float a = s_add;
    const int c = blockIdx.x * 256 + threadIdx.x;
    g_inv[c] = 1.0f / (g_nvar[c] + a);
}

// ---------------------------------------------------------------------------
// Pass 4: per-row copy + argmax of (h-nm)^2 * inv + winner fixup.
// grid = NB, block = 256, one row per block. R2's exact hot loop (2-way ILP,
// sequential strict-> compare chain, low regs, occ ~64% — best measured).
// ---------------------------------------------------------------------------
__global__ void __launch_bounds__(256, 6) k_punish(const float* __restrict__ h,
                                                   float* __restrict__ out) {
    const int row = blockIdx.x;
    const int tid = threadIdx.x;

    const float4* hrow = reinterpret_cast<const float4*>(h   + (size_t)row * ND);
    float4*       orow = reinterpret_cast<float4*>      (out + (size_t)row * ND);
    const float4* m4p  = reinterpret_cast<const float4*>(g_nmean);
    const float4* i4p  = reinterpret_cast<const float4*>(g_inv);

    float best = -1.0f;
    int   bidx = 0;

#pragma unroll
    for (int it = 0; it < ND / (256 * 4 * 2); ++it) {     // 8 steps, 2 chunks each
        const int j0 = it * 512 + tid;
        const int j1 = j0 + 256;

        float4 h0 = __ldcs(&hrow[j0]);
        float4 h1 = __ldcs(&hrow[j1]);
        float4 m0 = __ldg(&m4p[j0]);
        float4 m1 = __ldg(&m4p[j1]);
        float4 v0 = __ldg(&i4p[j0]);
        float4 v1 = __ldg(&i4p[j1]);

        __stcs(&orow[j0], h0);
        __stcs(&orow[j1], h1);

        const int c0 = j0 * 4, c1 = j1 * 4;
        float d, sc;
        d = h0.x - m0.x; sc = d * d * v0.x; if (sc > best) { best = sc; bidx = c0;     }
        d = h0.y - m0.y; sc = d * d * v0.y; if (sc > best) { best = sc; bidx = c0 + 1; }
        d = h0.z - m0.z; sc = d * d * v0.z; if (sc > best) { best = sc; bidx = c0 + 2; }
        d = h0.w - m0.w; sc = d * d * v0.w; if (sc > best) { best = sc; bidx = c0 + 3; }
        d = h1.x - m1.x; sc = d * d * v1.x; if (sc > best) { best = sc; bidx = c1;     }
        d = h1.y - m1.y; sc = d * d * v1.y; if (sc > best) { best = sc; bidx = c1 + 1; }
        d = h1.z - m1.z; sc = d * d * v1.z; if (sc > best) { best = sc; bidx = c1 + 2; }
        d = h1.w - m1.w; sc = d * d * v1.w; if (sc > best) { best = sc; bidx = c1 + 3; }
    }

    __shared__ float sbest[256];
    __shared__ int   sidx[256];
    sbest[tid] = best;
    sidx[tid]  = bidx;
    __syncthreads();
    for (int off = 128; off > 0; off >>= 1) {
        if (tid < off) {
            float ob = sbest[tid + off];
            int   oi = sidx[tid + off];
            if (ob > sbest[tid] || (ob == sbest[tid] && oi < sidx[tid])) {
                sbest[tid] = ob;
                sidx[tid]  = oi;
            }
        }
        __syncthreads();
    }
    if (tid == 0) {
        int w = sidx[0];
        out[(size_t)row * ND + w] = g_nmean[w];
    }
}

// ---------------------------------------------------------------------------
extern "C" void kernel_launch(void* const* d_in, const int* in_sizes, int n_in,
                              void* d_out, int out_size) {
    const float* h     = (const float*)d_in[0];
    const float* hmean = (const float*)d_in[1];
    const float* hvar  = (const float*)d_in[2];
    float* out = (float*)d_out;
    (void)in_sizes; (void)n_in; (void)out_size;

    dim3 g1(ND / (256 * 4), RSPLIT);
    k_colstats_partial<<<g1, 256>>>(h);
    k_colstats_finish<<<FIN_BLOCKS, 256>>>(hmean, hvar);
    k_scalar_inv<<<SI_BLOCKS, 256>>>();
    k_punish<<<NB, 256>>>(h, out);
}